// round 17
// baseline (speedup 1.0000x reference)
#include <cuda_runtime.h>
#include <cuda_bf16.h>

#define JNT 24
#define NPAIR (JNT / 2)
#define EPSF 1e-6f
#define SH_C0 0.28209479177387814f
#define SH_C1 0.4886025119029199f
#define C20 ( 1.0925484305920792f)
#define C21 (-1.0925484305920792f)
#define C22 ( 0.31539156525252005f)
#define C23 (-1.0925484305920792f)
#define C24 ( 0.5462742152960396f)

#define THREADS 256

typedef unsigned long long u64;

__device__ __forceinline__ float frcp(float x) {
    float r; asm("rcp.approx.ftz.f32 %0, %1;" : "=f"(r) : "f"(x)); return r;
}
__device__ __forceinline__ u64 pkbc(float v) {
    u64 r; asm("mov.b64 %0, {%1, %1};" : "=l"(r) : "f"(v)); return r;
}
__device__ __forceinline__ u64 pk2(float lo, float hi) {
    u64 r; asm("mov.b64 %0, {%1, %2};" : "=l"(r) : "f"(lo), "f"(hi)); return r;
}
__device__ __forceinline__ void upk2(float& lo, float& hi, u64 v) {
    asm("mov.b64 {%0, %1}, %2;" : "=f"(lo), "=f"(hi) : "l"(v));
}
__device__ __forceinline__ u64 ffma2(u64 a, u64 b, u64 c) {
    u64 d; asm("fma.rn.f32x2 %0, %1, %2, %3;" : "=l"(d) : "l"(a), "l"(b), "l"(c)); return d;
}
__device__ __forceinline__ u64 fmul2(u64 a, u64 b) {
    u64 d; asm("mul.rn.f32x2 %0, %1, %2;" : "=l"(d) : "l"(a), "l"(b)); return d;
}
__device__ __forceinline__ u64 fadd2(u64 a, u64 b) {
    u64 d; asm("add.rn.f32x2 %0, %1, %2;" : "=l"(d) : "l"(a), "l"(b)); return d;
}
__device__ __forceinline__ u64 fsub2(u64 a, u64 b) {
    u64 d; asm("sub.rn.f32x2 %0, %1, %2;" : "=l"(d) : "l"(a), "l"(b)); return d;
}
__device__ __forceinline__ float lanesum(u64 v) {
    float a, b; upk2(a, b, v); return a + b;
}

// Constant table: 12 float4 per JOINT-PAIR p (joints j=2p, k=2p+1).
// Every .xy / .zw half is a {val_j, val_k} lane-pair:
//  v0 : {-r00}p {-r01}p      v1 : {-r02}p {L0-t0}p
//  v2 : {-r10}p {-r11}p      v3 : {-r12}p {L1-t1}p
//  v4 : {-r20}p {-r21}p      v5 : {-r22}p {L2-t2}p
//  v6 : {f1'}p {f2'}p        v7 : {f3'}p {f4'}p
//  v8 : {f5'}p {f6''}p       v9 : {f7'}p {f8'}p
//  v10: {base}p {t0}p        v11: {t1}p {t2}p
__constant__ float4 cP[NPAIR * 12];

__global__ void prep_kernel(float4* __restrict__ dst,
                            const float* __restrict__ T,
                            const float* __restrict__ F,
                            const float* __restrict__ L)
{
    const int t = threadIdx.x;
    if (t >= NPAIR * 12) return;
    const int p = t / 12, m = t % 12;
    const int j = 2 * p, k = 2 * p + 1;
    const float* Tj = T + j * 16; const float* Tk = T + k * 16;
    const float* Fj = F + j * 9;  const float* Fk = F + k * 9;
    const float* Lj = L + j * 3;  const float* Lk = L + k * 3;
    float4 q;
    switch (m) {
        case 0:  q = make_float4(-Tj[0], -Tk[0], -Tj[1], -Tk[1]); break;
        case 1:  q = make_float4(-Tj[2], -Tk[2], Lj[0] - Tj[3], Lk[0] - Tk[3]); break;
        case 2:  q = make_float4(-Tj[4], -Tk[4], -Tj[5], -Tk[5]); break;
        case 3:  q = make_float4(-Tj[6], -Tk[6], Lj[1] - Tj[7], Lk[1] - Tk[7]); break;
        case 4:  q = make_float4(-Tj[8], -Tk[8], -Tj[9], -Tk[9]); break;
        case 5:  q = make_float4(-Tj[10], -Tk[10], Lj[2] - Tj[11], Lk[2] - Tk[11]); break;
        case 6:  q = make_float4(-SH_C1 * Fj[1], -SH_C1 * Fk[1],
                                  SH_C1 * Fj[2],  SH_C1 * Fk[2]); break;
        case 7:  q = make_float4(-SH_C1 * Fj[3], -SH_C1 * Fk[3],
                                  C20   * Fj[4],  C20   * Fk[4]); break;
        case 8:  q = make_float4( C21        * Fj[5],  C21        * Fk[5],
                                  3.f * C22  * Fj[6],  3.f * C22  * Fk[6]); break;
        case 9:  q = make_float4( C23 * Fj[7],  C23 * Fk[7],
                                  C24 * Fj[8],  C24 * Fk[8]); break;
        case 10: {
            const float bj = fmaf(SH_C0, Fj[0], 0.5f) - C22 * Fj[6];
            const float bk = fmaf(SH_C0, Fk[0], 0.5f) - C22 * Fk[6];
            q = make_float4(bj, bk, Tj[3], Tk[3]); break;
        }
        default: q = make_float4(Tj[7], Tk[7], Tj[11], Tk[11]); break;
    }
    dst[p * 12 + m] = q;
}

__global__ __launch_bounds__(THREADS)
void shcaster_kernel(const float* __restrict__ xyz,
                     const float* __restrict__ vdir,
                     float* __restrict__ out,       // [2*N*3]
                     int N)
{
    const int i = blockIdx.x * blockDim.x + threadIdx.x;
    if (i >= N) return;

    const float x0 = xyz[3 * i + 0];
    const float x1 = xyz[3 * i + 1];
    const float x2 = xyz[3 * i + 2];
    const float v0 = vdir[3 * i + 0];
    const float v1 = vdir[3 * i + 1];
    const float v2 = vdir[3 * i + 2];

    const u64 X0 = pkbc(x0);
    const u64 X1 = pkbc(x1);
    const u64 X2 = pkbc(x2);

    // lane = joint parity; epilogue collapses with one add each
    u64 WS  = 0ull;
    u64 A00 = 0ull, A01 = 0ull, A02 = 0ull;   // sum w * (-R) rows
    u64 A10 = 0ull, A11 = 0ull, A12 = 0ull;
    u64 A20 = 0ull, A21 = 0ull, A22 = 0ull;
    u64 AT0 = 0ull, AT1 = 0ull, AT2 = 0ull;   // sum w * t

#pragma unroll
    for (int p = 0; p < NPAIR; p++) {
        const float4 c0  = cP[p * 12 + 0];
        const float4 c1  = cP[p * 12 + 1];
        const float4 c2  = cP[p * 12 + 2];
        const float4 c3  = cP[p * 12 + 3];
        const float4 c4  = cP[p * 12 + 4];
        const float4 c5  = cP[p * 12 + 5];
        const float4 c6  = cP[p * 12 + 6];
        const float4 c7  = cP[p * 12 + 7];
        const float4 c8  = cP[p * 12 + 8];
        const float4 c9  = cP[p * 12 + 9];
        const float4 c10 = cP[p * 12 + 10];
        const float4 c11 = cP[p * 12 + 11];

        const u64 Pr00 = pk2(c0.x, c0.y), Pr01 = pk2(c0.z, c0.w);
        const u64 Pr02 = pk2(c1.x, c1.y), PDx  = pk2(c1.z, c1.w);
        const u64 Pr10 = pk2(c2.x, c2.y), Pr11 = pk2(c2.z, c2.w);
        const u64 Pr12 = pk2(c3.x, c3.y), PDy  = pk2(c3.z, c3.w);
        const u64 Pr20 = pk2(c4.x, c4.y), Pr21 = pk2(c4.z, c4.w);
        const u64 Pr22 = pk2(c5.x, c5.y), PDz  = pk2(c5.z, c5.w);
        const u64 Pf1  = pk2(c6.x, c6.y), Pf2  = pk2(c6.z, c6.w);
        const u64 Pf3  = pk2(c7.x, c7.y), Pf4  = pk2(c7.z, c7.w);
        const u64 Pf5  = pk2(c8.x, c8.y), Pf6  = pk2(c8.z, c8.w);
        const u64 Pf7  = pk2(c9.x, c9.y), Pf8  = pk2(c9.z, c9.w);
        const u64 Pb   = pk2(c10.x, c10.y), Pt0 = pk2(c10.z, c10.w);
        const u64 Pt1  = pk2(c11.x, c11.y), Pt2 = pk2(c11.z, c11.w);

        // d = (L - t) - R x  for BOTH joints (lanes)
        const u64 d0 = ffma2(Pr00, X0, ffma2(Pr01, X1, ffma2(Pr02, X2, PDx)));
        const u64 d1 = ffma2(Pr10, X0, ffma2(Pr11, X1, ffma2(Pr12, X2, PDy)));
        const u64 d2 = ffma2(Pr20, X0, ffma2(Pr21, X1, ffma2(Pr22, X2, PDz)));

        const u64 zz = fmul2(d2, d2);
        const u64 l2 = ffma2(d0, d0, ffma2(d1, d1, zz));

        float l2a, l2b;
        upk2(l2a, l2b, l2);
        const u64 invp = pk2(rsqrtf(l2a), rsqrtf(l2b));

        // SH dot in unnormalized d-space (both joints)
        const u64 lin = ffma2(Pf1, d1, ffma2(Pf2, d2, fmul2(Pf3, d0)));
        const u64 xy = fmul2(d0, d1);
        const u64 yz = fmul2(d1, d2);
        const u64 xz = fmul2(d0, d2);
        const u64 pm = fmul2(fsub2(d0, d1), fadd2(d0, d1));   // x^2 - y^2
        const u64 quad = ffma2(Pf4, xy,
                          ffma2(Pf5, yz,
                          ffma2(Pf6, zz,
                          ffma2(Pf7, xz, fmul2(Pf8, pm)))));
        const u64 rad = ffma2(ffma2(quad, invp, lin), invp, Pb);

        // weights (scalar per lane)
        float ra, rb, la, lb;
        upk2(ra, rb, rad);
        const u64 len = fmul2(l2, invp);
        upk2(la, lb, len);
        const float wa = fmaxf(fmaf(-la, frcp(fmaxf(ra, EPSF)), 1.0f), 0.f);
        const float wb = fmaxf(fmaf(-lb, frcp(fmaxf(rb, EPSF)), 1.0f), 0.f);
        const u64 wp = pk2(wa, wb);

        WS  = fadd2(WS, wp);
        A00 = ffma2(wp, Pr00, A00); A01 = ffma2(wp, Pr01, A01); A02 = ffma2(wp, Pr02, A02);
        A10 = ffma2(wp, Pr10, A10); A11 = ffma2(wp, Pr11, A11); A12 = ffma2(wp, Pr12, A12);
        A20 = ffma2(wp, Pr20, A20); A21 = ffma2(wp, Pr21, A21); A22 = ffma2(wp, Pr22, A22);
        AT0 = ffma2(wp, Pt0, AT0); AT1 = ffma2(wp, Pt1, AT1); AT2 = ffma2(wp, Pt2, AT2);
    }

    // collapse even/odd-joint lanes
    const float wsum = lanesum(WS);
    const float m00 = lanesum(A00), m01 = lanesum(A01), m02 = lanesum(A02);
    const float m10 = lanesum(A10), m11 = lanesum(A11), m12 = lanesum(A12);
    const float m20 = lanesum(A20), m21 = lanesum(A21), m22 = lanesum(A22);
    const float ta0 = lanesum(AT0), ta1 = lanesum(AT1), ta2 = lanesum(AT2);

    const float ic = frcp(fmaxf(wsum, EPSF));
    const bool valid = wsum > EPSF;

    // s = tacc - (mneg x)
    const float mx0 = fmaf(m00, x0, fmaf(m01, x1, m02 * x2));
    const float mx1 = fmaf(m10, x0, fmaf(m11, x1, m12 * x2));
    const float mx2 = fmaf(m20, x0, fmaf(m21, x1, m22 * x2));
    const float o0 = valid ? (ta0 - mx0) * ic : x0;
    const float o1 = valid ? (ta1 - mx1) * ic : x1;
    const float o2 = valid ? (ta2 - mx2) * ic : x2;

    // vd_out = (mneg v) * (-ic)
    const float nic = -ic;
    const float e0 = fmaf(m00, v0, fmaf(m01, v1, m02 * v2)) * nic;
    const float e1 = fmaf(m10, v0, fmaf(m11, v1, m12 * v2)) * nic;
    const float e2 = fmaf(m20, v0, fmaf(m21, v1, m22 * v2)) * nic;
    const float g0 = valid ? e0 : v0;
    const float g1 = valid ? e1 : v1;
    const float g2 = valid ? e2 : v2;

    float* o1p = out + 3 * (size_t)i;
    float* o2p = out + 3 * ((size_t)N + i);
    o1p[0] = o0; o1p[1] = o1; o1p[2] = o2;
    o2p[0] = g0; o2p[1] = g1; o2p[2] = g2;
}

extern "C" void kernel_launch(void* const* d_in, const int* in_sizes, int n_in,
                              void* d_out, int out_size)
{
    const float* xyz  = (const float*)d_in[0];
    const float* vdir = (const float*)d_in[1];
    const float* T    = (const float*)d_in[2];
    const float* F    = (const float*)d_in[3];
    const float* L    = (const float*)d_in[4];
    float* out        = (float*)d_out;

    const int N = in_sizes[0] / 3;

    void* cpPtr = nullptr;
    cudaGetSymbolAddress(&cpPtr, cP);
    prep_kernel<<<1, NPAIR * 12>>>((float4*)cpPtr, T, F, L);

    const int blocks = (N + THREADS - 1) / THREADS;
    shcaster_kernel<<<blocks, THREADS>>>(xyz, vdir, out, N);
}